// round 16
// baseline (speedup 1.0000x reference)
#include <cuda_runtime.h>
#include <cuda_fp16.h>
#include <cstdint>

// ---------------- problem constants ----------------
constexpr int cB = 32768, cS = 5, cD = 512, cE = 256, cNH = 4,
              cF = 2048, cL = 2, cC = 5;
constexpr int cBS = cB * cS;               // 163840 rows
constexpr int cZK = cS * cE;               // 1280, head input dim

// ---------------- scratch (device globals; no allocs) ----------------
__device__ __align__(16) float g_Z1[(size_t)cB * 128];
__device__ __align__(16) float g_Z2[(size_t)cB * 64];
__device__ __align__(16) float g_bias2[512];

__device__ __align__(16) __half g_X  [(size_t)cBS * cD];
__device__ __align__(16) __half g_Hh [(size_t)cBS * cE];   // residual stream fp16
__device__ __align__(16) __half g_Oh [(size_t)cBS * cE];   // attn out
__device__ __align__(16) __half g_T  [(size_t)cBS * 768];  // qkv fp16 / embed [BS,512]
__device__ __align__(16) __half g_Th [(size_t)cBS * cF];   // ff1 out fp16
__device__ __align__(16) __half g_Cbh[(size_t)cBS * cE];   // pre-LN out fp16

// weight fp16 pool (element offsets)
constexpr size_t OFF_GPS = 0;                       // 256*512
constexpr size_t OFF_ANG = OFF_GPS + 131072;        // contiguous after GPS
constexpr size_t OFF_QKV = OFF_ANG + 131072;        // L*768*256
constexpr size_t OFF_OW  = OFF_QKV + 393216;        // L*256*256
constexpr size_t OFF_FF1 = OFF_OW  + 131072;        // L*2048*256
constexpr size_t OFF_FF2 = OFF_FF1 + 1048576;       // L*256*2048
constexpr size_t OFF_FC1 = OFF_FF2 + 1048576;       // 128*1280
constexpr size_t W_TOTAL = OFF_FC1 + 163840;
__device__ __align__(16) __half g_W[W_TOTAL];

// =================== helpers ===================
__device__ __forceinline__ uint32_t smem_u32(const void* p) {
    uint32_t a;
    asm("{ .reg .u64 t; cvta.to.shared.u64 t, %1; cvt.u32.u64 %0, t; }"
        : "=r"(a) : "l"(p));
    return a;
}
__device__ __forceinline__ void ldsm4(uint32_t& r0, uint32_t& r1,
                                      uint32_t& r2, uint32_t& r3, uint32_t addr) {
    asm volatile("ldmatrix.sync.aligned.m8n8.x4.shared.b16 {%0,%1,%2,%3}, [%4];"
                 : "=r"(r0), "=r"(r1), "=r"(r2), "=r"(r3) : "r"(addr));
}
__device__ __forceinline__ void mma16816h(float* d, const uint32_t* a,
                                          uint32_t b0, uint32_t b1) {
    asm volatile(
        "mma.sync.aligned.m16n8k16.row.col.f32.f16.f16.f32 "
        "{%0,%1,%2,%3}, {%4,%5,%6,%7}, {%8,%9}, {%0,%1,%2,%3};"
        : "+f"(d[0]), "+f"(d[1]), "+f"(d[2]), "+f"(d[3])
        : "r"(a[0]), "r"(a[1]), "r"(a[2]), "r"(a[3]), "r"(b0), "r"(b1));
}
__device__ __forceinline__ void cpasync16(uint32_t dst, const void* src) {
    asm volatile("cp.async.cg.shared.global [%0], [%1], 16;" :: "r"(dst), "l"(src));
}
#define CP_COMMIT() asm volatile("cp.async.commit_group;" ::: "memory")
#define CP_WAIT2()  asm volatile("cp.async.wait_group 2;" ::: "memory")

__device__ __forceinline__ uint32_t pack_h2(float x, float y) {
    __half2 h = __float22half2_rn(make_float2(x, y));
    return *(uint32_t*)&h;
}
__device__ __forceinline__ float2 unpack_h2(uint32_t u) {
    return __half22float2(*(__half2*)&u);
}

// =================== fp32 -> fp16 converter ===================
__global__ __launch_bounds__(256) void convert_h(
    const float* __restrict__ src, __half* __restrict__ dst, size_t n4)
{
    const size_t i = (size_t)blockIdx.x * blockDim.x + threadIdx.x;
    if (i >= n4) return;
    float4 v = ((const float4*)src)[i];
    ((uint2*)dst)[i] = make_uint2(pack_h2(v.x, v.y), pack_h2(v.z, v.w));
}

// concat two bias vectors [n] -> dst[2n]
__global__ void concat2_kernel(const float* __restrict__ a, const float* __restrict__ b,
                               float* __restrict__ dst, int n)
{
    const int i = blockIdx.x * blockDim.x + threadIdx.x;
    if (i < n) dst[i] = a[i];
    else if (i < 2 * n) dst[i] = b[i - n];
}

// =================== persistent tensor-core GEMM ================================
// CTA tile 128x128, warp tile 32x64, 8 warps as 4(M)x2(N). single-pass fp16.
// 4-stage cp.async ring, ONE __syncthreads per chunk, pipeline primed ACROSS
// M-tiles (persistent over M: mt = blockIdx.y, += gridDim.y).
// MT = M/128. N%128==0, K%32==0, K>=96.
constexpr int SROW = 80;                   // smem row stride (bytes)
constexpr int SBUF = 128 * SROW;           // 10240 B per operand
constexpr int STAGE_B = 2 * SBUF;          // 20480 B per stage (A, W)
constexpr int NSTG = 4;
constexpr int GEMM_SMEM = NSTG * STAGE_B;  // 81920 B

template<bool RELU, bool PAIR>
__global__ __launch_bounds__(256, 2) void gemm_mma(
    const __half* __restrict__ A, const __half* __restrict__ W,
    const float* __restrict__ bias,
    float* __restrict__ Cf, __half* __restrict__ Ch,
    int MT, int N, int K)
{
    extern __shared__ char sm[];
    const uint32_t sbase = smem_u32(sm);

    const int tid = threadIdx.x;
    const int wid = tid >> 5, lane = tid & 31;
    const int bn = blockIdx.x * 128;
    const int wm = (wid >> 1) * 32, wn = (wid & 1) * 64;

    // loader mapping: thread -> row tid/2 (0..127), 16B chunks q0,q0+1, q0=(tid&1)*2
    const int lrow = tid >> 1;
    const int q0 = (tid & 1) * 2;
    const size_t aoff_t = (size_t)lrow * K + q0 * 8;          // per-thread A offset in a tile
    const __half* pWb = W + (size_t)(bn + lrow) * K + q0 * 8; // fixed per CTA
    const uint32_t soff = (uint32_t)(lrow * SROW + q0 * 16);

    const int nk = K / 32;

    // lookahead issue state (global chunk stream over this CTA's tiles)
    int it_t = 0, it_c = 0, it_s = 0;
    auto issue_next = [&]() {
        const int mt = (int)blockIdx.y + it_t * (int)gridDim.y;
        if (mt < MT) {
            const uint32_t st = sbase + it_s * STAGE_B + soff;
            const __half* pa = A + (size_t)mt * 128 * K + aoff_t + (size_t)it_c * 32;
            const __half* pw = pWb + (size_t)it_c * 32;
            cpasync16(st,              pa);
            cpasync16(st + 16,         pa + 8);
            cpasync16(st + SBUF,       pw);
            cpasync16(st + SBUF + 16,  pw + 8);
        }
        CP_COMMIT();
        if (++it_c == nk) { it_c = 0; ++it_t; }
        it_s = (it_s + 1) & 3;
    };

    const uint32_t a_off = (uint32_t)((wm + (lane & 15)) * SROW + (lane >> 4) * 16);
    const uint32_t w_off = (uint32_t)((wn + (lane & 7) + ((lane >> 4) & 1) * 8) * SROW
                                      + ((lane >> 3) & 1) * 16);
    const int erow = (lane >> 2);
    const int ecol = (lane & 3) * 2;

    issue_next(); issue_next(); issue_next();

    int cs = 0;  // compute stage ring
    for (int mt = blockIdx.y; mt < MT; mt += gridDim.y) {
        float acc[2][8][4];
#pragma unroll
        for (int i = 0; i < 2; i++)
#pragma unroll
            for (int j = 0; j < 8; j++)
#pragma unroll
                for (int k = 0; k < 4; k++) acc[i][j][k] = 0.f;

        for (int c = 0; c < nk; ++c) {
            CP_WAIT2();           // chunk arrived (<=2 newer groups pending)
            __syncthreads();      // prior stage fully consumed by all warps
            issue_next();

            const uint32_t sA = sbase + cs * STAGE_B;
            const uint32_t sW = sA + SBUF;
#pragma unroll
            for (int ks = 0; ks < 2; ++ks) {
                const uint32_t ko = ks * 32;
                uint32_t aF[2][4], bF[8][2];
#pragma unroll
                for (int mf = 0; mf < 2; mf++)
                    ldsm4(aF[mf][0], aF[mf][1], aF[mf][2], aF[mf][3],
                          sA + a_off + mf * (16 * SROW) + ko);
#pragma unroll
                for (int p = 0; p < 4; p++) {
                    uint32_t r0, r1, r2, r3;
                    ldsm4(r0, r1, r2, r3, sW + w_off + p * (16 * SROW) + ko);
                    bF[2*p][0] = r0; bF[2*p][1] = r1;
                    bF[2*p+1][0] = r2; bF[2*p+1][1] = r3;
                }
#pragma unroll
                for (int mf = 0; mf < 2; mf++)
#pragma unroll
                    for (int nf = 0; nf < 8; nf++)
                        mma16816h(acc[mf][nf], aF[mf], bF[nf][0], bF[nf][1]);
            }
            cs = (cs + 1) & 3;
        }

        // epilogue (register-only; overlaps with in-flight loads of next tile)
        const int bm = mt * 128;
#pragma unroll
        for (int nf = 0; nf < 8; nf++) {
            const int col = bn + wn + nf * 8 + ecol;
            const float2 bv = *(const float2*)&bias[col];
#pragma unroll
            for (int mf = 0; mf < 2; mf++) {
                const int r0 = bm + wm + mf * 16 + erow;
                float2 o0, o1;
                o0.x = acc[mf][nf][0] + bv.x; o0.y = acc[mf][nf][1] + bv.y;
                o1.x = acc[mf][nf][2] + bv.x; o1.y = acc[mf][nf][3] + bv.y;
                if (RELU) {
                    o0.x = fmaxf(o0.x, 0.f); o0.y = fmaxf(o0.y, 0.f);
                    o1.x = fmaxf(o1.x, 0.f); o1.y = fmaxf(o1.y, 0.f);
                }
                if (PAIR) {
                    *(uint32_t*)&Ch[(size_t)r0 * N + col] = pack_h2(o0.x, o0.y);
                    *(uint32_t*)&Ch[(size_t)(r0 + 8) * N + col] = pack_h2(o1.x, o1.y);
                } else {
                    *(float2*)&Cf[(size_t)r0 * N + col] = o0;
                    *(float2*)&Cf[(size_t)(r0 + 8) * N + col] = o1;
                }
            }
        }
    }
}

// =================== small SIMT GEMM (head fc2) ===================
__global__ __launch_bounds__(256) void gemm_bias(
    const float* __restrict__ A, const float* __restrict__ W,
    const float* __restrict__ bias, float* __restrict__ C,
    int M, int N, int K)
{
    __shared__ float As[16][68];
    __shared__ float Ws[16][68];
    const int t  = threadIdx.x;
    const int bm = blockIdx.y * 64, bn = blockIdx.x * 64;
    const int tm = (t >> 4) << 2;
    const int tn = (t & 15) << 2;
    const int lr = t >> 2;
    const int lc = (t & 3) << 2;

    float acc[4][4] = {};
    const float* Ap = A + (size_t)(bm + lr) * K + lc;
    const float* Wp = W + (size_t)(bn + lr) * K + lc;

    for (int k0 = 0; k0 < K; k0 += 16) {
        float4 av = *(const float4*)(Ap + k0);
        float4 wv = (bn + lr < N) ? *(const float4*)(Wp + k0) : make_float4(0, 0, 0, 0);
        As[lc+0][lr]=av.x; As[lc+1][lr]=av.y; As[lc+2][lr]=av.z; As[lc+3][lr]=av.w;
        Ws[lc+0][lr]=wv.x; Ws[lc+1][lr]=wv.y; Ws[lc+2][lr]=wv.z; Ws[lc+3][lr]=wv.w;
        __syncthreads();
#pragma unroll
        for (int k = 0; k < 16; k++) {
            float4 a4 = *(const float4*)&As[k][tm];
            float4 w4 = *(const float4*)&Ws[k][tn];
            const float ar[4] = {a4.x, a4.y, a4.z, a4.w};
            const float wr[4] = {w4.x, w4.y, w4.z, w4.w};
#pragma unroll
            for (int r = 0; r < 4; r++)
#pragma unroll
                for (int c = 0; c < 4; c++)
                    acc[r][c] = fmaf(ar[r], wr[c], acc[r][c]);
        }
        __syncthreads();
    }
    if (bn + tn >= N) return;
    float4 bv = *(const float4*)&bias[bn + tn];
    const float bb[4] = {bv.x, bv.y, bv.z, bv.w};
#pragma unroll
    for (int r = 0; r < 4; r++) {
        float4 o; float* op = (float*)&o;
#pragma unroll
        for (int c = 0; c < 4; c++) op[c] = acc[r][c] + bb[c];
        *(float4*)&C[(size_t)(bm + tm + r) * N + bn + tn] = o;
    }
}

// =================== expert select from fused embed [BS,512] ===================
__global__ __launch_bounds__(256) void select_kernel(
    const __half* __restrict__ E2, const int* __restrict__ ST,
    __half* __restrict__ Hh)
{
    const size_t i = (size_t)blockIdx.x * blockDim.x + threadIdx.x;  // uint2 idx of output
    const int row = (int)(i >> 6);                                   // 64 uint2/row (256 halves)
    const int c4  = (int)(i & 63);
    const __half* src = E2 + (size_t)row * 512 + (ST[row] == 0 ? 0 : 256);
    ((uint2*)Hh)[i] = ((const uint2*)src)[c4];
}

// =================== attention: one warp per (batch, head), fp16 in/out =============
__global__ __launch_bounds__(256) void attn_kernel(
    const __half* __restrict__ QKV, __half* __restrict__ Oh)
{
    const int gwarp = (blockIdx.x * blockDim.x + threadIdx.x) >> 5;
    const int lane  = threadIdx.x & 31;
    if (gwarp >= cB * cNH) return;
    const int b = gwarp >> 2, h = gwarp & 3;

    const __half* base = QKV + (size_t)b * cS * 768 + h * 64 + 2 * lane;
    float q[cS][2], kk[cS][2], vv[cS][2];
#pragma unroll
    for (int s = 0; s < cS; s++) {
        const __half* r = base + s * 768;
        float2 qv = unpack_h2(*(const uint32_t*)(r));
        float2 kv = unpack_h2(*(const uint32_t*)(r + 256));
        float2 vw = unpack_h2(*(const uint32_t*)(r + 512));
        q [s][0] = qv.x; q [s][1] = qv.y;
        kk[s][0] = kv.x; kk[s][1] = kv.y;
        vv[s][0] = vw.x; vv[s][1] = vw.y;
    }
    float sc[cS][cS];
#pragma unroll
    for (int i = 0; i < cS; i++)
#pragma unroll
        for (int j = 0; j < cS; j++) {
            float p = q[i][0] * kk[j][0] + q[i][1] * kk[j][1];
#pragma unroll
            for (int o = 16; o > 0; o >>= 1) p += __shfl_xor_sync(0xFFFFFFFFu, p, o);
            sc[i][j] = p * 0.125f;
        }
#pragma unroll
    for (int i = 0; i < cS; i++) {
        float m = sc[i][0];
#pragma unroll
        for (int j = 1; j < cS; j++) m = fmaxf(m, sc[i][j]);
        float e[cS], s = 0.f;
#pragma unroll
        for (int j = 0; j < cS; j++) { e[j] = expf(sc[i][j] - m); s += e[j]; }
        const float inv = 1.f / s;
        float o0 = 0.f, o1 = 0.f;
#pragma unroll
        for (int j = 0; j < cS; j++) {
            const float a = e[j] * inv;
            o0 = fmaf(a, vv[j][0], o0);
            o1 = fmaf(a, vv[j][1], o1);
        }
        const size_t off = (size_t)(b * cS + i) * cE + h * 64 + 2 * lane;
        *(uint32_t*)&Oh[off] = pack_h2(o0, o1);
    }
}

// =================== fused residual + layernorm (fp16 in/out, fp32 math) ============
__global__ __launch_bounds__(256) void add_ln_kernel(
    const __half* __restrict__ Hin, const __half* __restrict__ Cin,
    const float* __restrict__ G, const float* __restrict__ Bv,
    __half* __restrict__ Hout)
{
    const int row  = blockIdx.x * 8 + (threadIdx.x >> 5);
    const int lane = threadIdx.x & 31;
    const size_t rb = (size_t)row * cE;

    float2 v[4];
    float s = 0.f;
#pragma unroll
    for (int i = 0; i < 4; i++) {
        const int e = i * 64 + lane * 2;
        float2 a = unpack_h2(*(const uint32_t*)&Hin[rb + e]);
        float2 b = unpack_h2(*(const uint32_t*)&Cin[rb + e]);
        v[i].x = a.x + b.x; v[i].y = a.y + b.y;
        s += v[i].x + v[i].y;
    }
#pragma unroll
    for (int o = 16; o > 0; o >>= 1) s += __shfl_xor_sync(0xFFFFFFFFu, s, o);
    const float mean = s * (1.f / cE);

    float vs = 0.f;
#pragma unroll
    for (int i = 0; i < 4; i++) {
        const float dx = v[i].x - mean, dy = v[i].y - mean;
        vs += dx * dx + dy * dy;
    }
#pragma unroll
    for (int o = 16; o > 0; o >>= 1) vs += __shfl_xor_sync(0xFFFFFFFFu, vs, o);
    const float rs = rsqrtf(vs * (1.f / cE) + 1e-5f);

#pragma unroll
    for (int i = 0; i < 4; i++) {
        const int e = i * 64 + lane * 2;
        const float2 g = *(const float2*)&G[e];
        const float2 b = *(const float2*)&Bv[e];
        float ox = (v[i].x - mean) * rs * g.x + b.x;
        float oy = (v[i].y - mean) * rs * g.y + b.y;
        *(uint32_t*)&Hout[rb + e] = pack_h2(ox, oy);
    }
}

// =================== final tiny projection ===================
__global__ __launch_bounds__(256) void out_kernel(
    const float* __restrict__ Z, const float* __restrict__ OW,
    const float* __restrict__ OB, float* __restrict__ OUT)
{
    const int b = blockIdx.x * blockDim.x + threadIdx.x;
    if (b >= cB) return;
    float acc[cC];
#pragma unroll
    for (int c = 0; c < cC; c++) acc[c] = OB[c];
    const float* zr = Z + (size_t)b * 64;
    for (int k = 0; k < 64; k++) {
        const float z = zr[k];
#pragma unroll
        for (int c = 0; c < cC; c++) acc[c] = fmaf(z, OW[c * 64 + k], acc[c]);
    }
#pragma unroll
    for (int c = 0; c < cC; c++) OUT[(size_t)b * cC + c] = acc[c];
}

// ---------------- launch ----------------
template<typename T>
static T* symaddr(const void* sym) {
    void* p = nullptr;
    cudaGetSymbolAddress(&p, sym);
    return (T*)p;
}
static void conv_w(const float* src, __half* dst, size_t n) {
    const size_t n4 = n / 4;
    convert_h<<<(unsigned)((n4 + 255) / 256), 256>>>(src, dst, n4);
}
static inline int pgrid_for(int NT, int MT) {
    int p = 296 / NT;
    if (p < 1) p = 1;
    if (p > MT) p = MT;
    return p;
}

extern "C" void kernel_launch(void* const* d_in, const int* in_sizes, int n_in,
                              void* d_out, int out_size)
{
    const float* x       = (const float*)d_in[0];
    const int*   st      = (const int*)  d_in[1];
    const float* gps_w   = (const float*)d_in[2];
    const float* gps_b   = (const float*)d_in[3];
    const float* ang_w   = (const float*)d_in[4];
    const float* ang_b   = (const float*)d_in[5];
    const float* qkv_w   = (const float*)d_in[6];
    const float* qkv_b   = (const float*)d_in[7];
    const float* attn_ow = (const float*)d_in[8];
    const float* attn_ob = (const float*)d_in[9];
    const float* ln1_g   = (const float*)d_in[10];
    const float* ln1_b   = (const float*)d_in[11];
    const float* ff1_w   = (const float*)d_in[12];
    const float* ff1_b   = (const float*)d_in[13];
    const float* ff2_w   = (const float*)d_in[14];
    const float* ff2_b   = (const float*)d_in[15];
    const float* ln2_g   = (const float*)d_in[16];
    const float* ln2_b   = (const float*)d_in[17];
    const float* fc1_w   = (const float*)d_in[18];
    const float* fc1_b   = (const float*)d_in[19];
    const float* fc2_w   = (const float*)d_in[20];
    const float* fc2_b   = (const float*)d_in[21];
    const float* out_w   = (const float*)d_in[22];
    const float* out_b   = (const float*)d_in[23];
    float* out = (float*)d_out;

    float* Z1  = symaddr<float>(g_Z1);
    float* Z2  = symaddr<float>(g_Z2);
    float* B2  = symaddr<float>(g_bias2);
    __half* X   = symaddr<__half>(g_X);
    __half* Hh  = symaddr<__half>(g_Hh);
    __half* Oh  = symaddr<__half>(g_Oh);
    __half* T   = symaddr<__half>(g_T);
    __half* Th  = symaddr<__half>(g_Th);
    __half* Cbh = symaddr<__half>(g_Cbh);
    __half* W   = symaddr<__half>(g_W);

    static bool attr_set = false;
    if (!attr_set) {
        cudaFuncSetAttribute((const void*)gemm_mma<false,false>,
                             cudaFuncAttributeMaxDynamicSharedMemorySize, GEMM_SMEM);
        cudaFuncSetAttribute((const void*)gemm_mma<true,false>,
                             cudaFuncAttributeMaxDynamicSharedMemorySize, GEMM_SMEM);
        cudaFuncSetAttribute((const void*)gemm_mma<false,true>,
                             cudaFuncAttributeMaxDynamicSharedMemorySize, GEMM_SMEM);
        cudaFuncSetAttribute((const void*)gemm_mma<true,true>,
                             cudaFuncAttributeMaxDynamicSharedMemorySize, GEMM_SMEM);
        attr_set = true;
    }

    // 0. convert input + weights to fp16; concat embed biases
    conv_w(x, X, (size_t)cBS * cD);
    conv_w(gps_w,   W + OFF_GPS, 131072);
    conv_w(ang_w,   W + OFF_ANG, 131072);
    conv_w(qkv_w,   W + OFF_QKV, 393216);
    conv_w(attn_ow, W + OFF_OW,  131072);
    conv_w(ff1_w,   W + OFF_FF1, 1048576);
    conv_w(ff2_w,   W + OFF_FF2, 1048576);
    conv_w(fc1_w,   W + OFF_FC1, 163840);
    concat2_kernel<<<2, 256>>>(gps_b, ang_b, B2, 256);

    const int MT = cBS / 128;   // 1280 row tiles

    // 1. fused dual-expert embed (N=512: [gps|ang]) + select
    gemm_mma<true,true><<<dim3(4, pgrid_for(4, MT)), 256, GEMM_SMEM>>>(
        X, W + OFF_GPS, B2, nullptr, T, MT, 512, cD);
    select_kernel<<<(cBS * cE / 4) / 256, 256>>>(T, st, Hh);

    // 2. transformer layers
    for (int l = 0; l < cL; l++) {
        const __half* qw  = W + OFF_QKV + (size_t)l * 768 * cE;
        const __half* ow  = W + OFF_OW  + (size_t)l * cE * cE;
        const __half* f1w = W + OFF_FF1 + (size_t)l * cF * cE;
        const __half* f2w = W + OFF_FF2 + (size_t)l * cE * cF;
        const float* qb  = qkv_b   + (size_t)l * 3 * cE;
        const float* ob  = attn_ob + (size_t)l * cE;
        const float* f1b = ff1_b   + (size_t)l * cF;
        const float* f2b = ff2_b   + (size_t)l * cE;

        gemm_mma<false,true><<<dim3(6, pgrid_for(6, MT)), 256, GEMM_SMEM>>>(
            Hh, qw, qb, nullptr, T, MT, 768, cE);
        attn_kernel<<<(cB * cNH * 32) / 256, 256>>>(T, Oh);
        gemm_mma<false,true><<<dim3(2, pgrid_for(2, MT)), 256, GEMM_SMEM>>>(
            Oh, ow, ob, nullptr, Cbh, MT, cE, cE);
        add_ln_kernel<<<cBS / 8, 256>>>(Hh, Cbh, ln1_g + l * cE, ln1_b + l * cE, Hh);
        gemm_mma<true,true><<<dim3(16, pgrid_for(16, MT)), 256, GEMM_SMEM>>>(
            Hh, f1w, f1b, nullptr, Th, MT, cF, cE);
        gemm_mma<false,true><<<dim3(2, pgrid_for(2, MT)), 256, GEMM_SMEM>>>(
            Th, f2w, f2b, nullptr, Cbh, MT, cE, cF);
        add_ln_kernel<<<cBS / 8, 256>>>(Hh, Cbh, ln2_g + l * cE, ln2_b + l * cE, Hh);
    }

    // 3. head: Hh viewed as [B,1280]
    gemm_mma<false,false><<<dim3(1, pgrid_for(1, cB / 128)), 256, GEMM_SMEM>>>(
        Hh, W + OFF_FC1, fc1_b, Z1, nullptr, cB / 128, 128, cZK);
    gemm_bias<<<dim3(1, cB / 64), 256>>>(Z1, fc2_w, fc2_b, Z2, cB, 64, 128);
    out_kernel<<<cB / 256, 256>>>(Z2, out_w, out_b, out);
}

// round 17
// speedup vs baseline: 1.0565x; 1.0565x over previous
#include <cuda_runtime.h>
#include <cuda_fp16.h>
#include <cstdint>

// ---------------- problem constants ----------------
constexpr int cB = 32768, cS = 5, cD = 512, cE = 256, cNH = 4,
              cF = 2048, cL = 2, cC = 5;
constexpr int cBS = cB * cS;               // 163840 rows
constexpr int cZK = cS * cE;               // 1280, head input dim

// ---------------- scratch (device globals; no allocs) ----------------
__device__ __align__(16) float g_Z1[(size_t)cB * 128];
__device__ __align__(16) float g_Z2[(size_t)cB * 64];
__device__ __align__(16) float g_bias2[512];

__device__ __align__(16) __half g_X  [(size_t)cBS * cD];
__device__ __align__(16) __half g_Hh [(size_t)cBS * cE];   // residual stream fp16
__device__ __align__(16) __half g_Oh [(size_t)cBS * cE];   // attn out
__device__ __align__(16) __half g_T  [(size_t)cBS * 768];  // qkv fp16 / embed [BS,512]
__device__ __align__(16) __half g_Th [(size_t)cBS * cF];   // ff1 out fp16
__device__ __align__(16) __half g_Cbh[(size_t)cBS * cE];   // pre-LN out fp16

// weight fp16 pool (element offsets)
constexpr size_t OFF_GPS = 0;                       // 256*512
constexpr size_t OFF_ANG = OFF_GPS + 131072;        // contiguous after GPS
constexpr size_t OFF_QKV = OFF_ANG + 131072;        // L*768*256
constexpr size_t OFF_OW  = OFF_QKV + 393216;        // L*256*256
constexpr size_t OFF_FF1 = OFF_OW  + 131072;        // L*2048*256
constexpr size_t OFF_FF2 = OFF_FF1 + 1048576;       // L*256*2048
constexpr size_t OFF_FC1 = OFF_FF2 + 1048576;       // 128*1280
constexpr size_t W_TOTAL = OFF_FC1 + 163840;
__device__ __align__(16) __half g_W[W_TOTAL];

// =================== helpers ===================
__device__ __forceinline__ uint32_t smem_u32(const void* p) {
    uint32_t a;
    asm("{ .reg .u64 t; cvta.to.shared.u64 t, %1; cvt.u32.u64 %0, t; }"
        : "=r"(a) : "l"(p));
    return a;
}
__device__ __forceinline__ void ldsm4(uint32_t& r0, uint32_t& r1,
                                      uint32_t& r2, uint32_t& r3, uint32_t addr) {
    asm volatile("ldmatrix.sync.aligned.m8n8.x4.shared.b16 {%0,%1,%2,%3}, [%4];"
                 : "=r"(r0), "=r"(r1), "=r"(r2), "=r"(r3) : "r"(addr));
}
__device__ __forceinline__ void mma16816h(float* d, const uint32_t* a,
                                          uint32_t b0, uint32_t b1) {
    asm volatile(
        "mma.sync.aligned.m16n8k16.row.col.f32.f16.f16.f32 "
        "{%0,%1,%2,%3}, {%4,%5,%6,%7}, {%8,%9}, {%0,%1,%2,%3};"
        : "+f"(d[0]), "+f"(d[1]), "+f"(d[2]), "+f"(d[3])
        : "r"(a[0]), "r"(a[1]), "r"(a[2]), "r"(a[3]), "r"(b0), "r"(b1));
}
__device__ __forceinline__ void cpasync16(uint32_t dst, const void* src) {
    asm volatile("cp.async.cg.shared.global [%0], [%1], 16;" :: "r"(dst), "l"(src));
}
#define CP_COMMIT() asm volatile("cp.async.commit_group;" ::: "memory")
#define CP_WAIT2()  asm volatile("cp.async.wait_group 2;" ::: "memory")

__device__ __forceinline__ uint32_t pack_h2(float x, float y) {
    __half2 h = __float22half2_rn(make_float2(x, y));
    return *(uint32_t*)&h;
}
__device__ __forceinline__ float2 unpack_h2(uint32_t u) {
    return __half22float2(*(__half2*)&u);
}

// =================== fp32 -> fp16 converter ===================
__global__ __launch_bounds__(256) void convert_h(
    const float* __restrict__ src, __half* __restrict__ dst, size_t n4)
{
    const size_t i = (size_t)blockIdx.x * blockDim.x + threadIdx.x;
    if (i >= n4) return;
    float4 v = ((const float4*)src)[i];
    ((uint2*)dst)[i] = make_uint2(pack_h2(v.x, v.y), pack_h2(v.z, v.w));
}

// concat two bias vectors [n] -> dst[2n]
__global__ void concat2_kernel(const float* __restrict__ a, const float* __restrict__ b,
                               float* __restrict__ dst, int n)
{
    const int i = blockIdx.x * blockDim.x + threadIdx.x;
    if (i < n) dst[i] = a[i];
    else if (i < 2 * n) dst[i] = b[i - n];
}

// =================== tensor-core GEMM: CTA 128x128, warp tile 32x64 ================
// 8 warps as 4(M) x 2(N). single-pass fp16: C = A.W^T + bias.
// 4-stage cp.async, ONE __syncthreads per chunk (CUTLASS-style multistage).
// M%128==0, N%128==0, K%32==0, K>=96.
constexpr int SROW = 80;                   // smem row stride (bytes)
constexpr int SBUF = 128 * SROW;           // 10240 B per operand
constexpr int STAGE_B = 2 * SBUF;          // 20480 B per stage (A, W)
constexpr int NSTG = 4;
constexpr int GEMM_SMEM = NSTG * STAGE_B;  // 81920 B

template<bool RELU, bool PAIR>
__global__ __launch_bounds__(256, 2) void gemm_mma(
    const __half* __restrict__ A, const __half* __restrict__ W,
    const float* __restrict__ bias,
    float* __restrict__ Cf, __half* __restrict__ Ch,
    int M, int N, int K)
{
    extern __shared__ char sm[];
    const uint32_t sbase = smem_u32(sm);

    const int tid = threadIdx.x;
    const int wid = tid >> 5, lane = tid & 31;
    const int bm = blockIdx.y * 128, bn = blockIdx.x * 128;
    const int wm = (wid >> 1) * 32, wn = (wid & 1) * 64;

    // loader: thread -> row tid/2 (0..127), 16B chunks q0, q0+1 where q0=(tid&1)*2
    const int lrow = tid >> 1;
    const int q0 = (tid & 1) * 2;
    const __half* pA = A + (size_t)(bm + lrow) * K + q0 * 8;
    const __half* pW = W + (size_t)(bn + lrow) * K + q0 * 8;
    const uint32_t soff = (uint32_t)(lrow * SROW + q0 * 16);

    auto issue_stage = [&](int c, int s) {
        const uint32_t st = sbase + s * STAGE_B + soff;
        const size_t ko = (size_t)c * 32;
        cpasync16(st,               pA + ko);
        cpasync16(st + 16,          pA + ko + 8);
        cpasync16(st + SBUF,        pW + ko);
        cpasync16(st + SBUF + 16,   pW + ko + 8);
    };

    float acc[2][8][4];
#pragma unroll
    for (int i = 0; i < 2; i++)
#pragma unroll
        for (int j = 0; j < 8; j++)
#pragma unroll
            for (int k = 0; k < 4; k++) acc[i][j][k] = 0.f;

    const uint32_t a_off = (uint32_t)((wm + (lane & 15)) * SROW + (lane >> 4) * 16);
    const uint32_t w_off = (uint32_t)((wn + (lane & 7) + ((lane >> 4) & 1) * 8) * SROW
                                      + ((lane >> 3) & 1) * 16);

    const int nk = K / 32;
    issue_stage(0, 0); CP_COMMIT();
    issue_stage(1, 1); CP_COMMIT();
    issue_stage(2, 2); CP_COMMIT();

    for (int c = 0; c < nk; ++c) {
        const int s = c & 3;
        // chunk c arrived when <=2 newer groups pending
        CP_WAIT2();
        // all warps done reading stage (c-1)&3 == (c+3)&3  -> safe to overwrite
        __syncthreads();
        if (c + 3 < nk) issue_stage(c + 3, (c + 3) & 3);
        CP_COMMIT();

        const uint32_t sA = sbase + s * STAGE_B;
        const uint32_t sW = sA + SBUF;

#pragma unroll
        for (int ks = 0; ks < 2; ++ks) {
            const uint32_t ko = ks * 32;
            uint32_t aF[2][4], bF[8][2];
#pragma unroll
            for (int mf = 0; mf < 2; mf++)
                ldsm4(aF[mf][0], aF[mf][1], aF[mf][2], aF[mf][3],
                      sA + a_off + mf * (16 * SROW) + ko);
#pragma unroll
            for (int p = 0; p < 4; p++) {
                uint32_t r0, r1, r2, r3;
                ldsm4(r0, r1, r2, r3, sW + w_off + p * (16 * SROW) + ko);
                bF[2*p][0] = r0; bF[2*p][1] = r1;
                bF[2*p+1][0] = r2; bF[2*p+1][1] = r3;
            }
#pragma unroll
            for (int mf = 0; mf < 2; mf++)
#pragma unroll
                for (int nf = 0; nf < 8; nf++)
                    mma16816h(acc[mf][nf], aF[mf], bF[nf][0], bF[nf][1]);
        }
    }

    // epilogue (register-only inputs; no trailing barrier needed)
    const int erow = (lane >> 2);
    const int ecol = (lane & 3) * 2;
#pragma unroll
    for (int nf = 0; nf < 8; nf++) {
        const int col = bn + wn + nf * 8 + ecol;
        const float2 bv = *(const float2*)&bias[col];
#pragma unroll
        for (int mf = 0; mf < 2; mf++) {
            const int r0 = bm + wm + mf * 16 + erow;
            float2 o0, o1;
            o0.x = acc[mf][nf][0] + bv.x; o0.y = acc[mf][nf][1] + bv.y;
            o1.x = acc[mf][nf][2] + bv.x; o1.y = acc[mf][nf][3] + bv.y;
            if (RELU) {
                o0.x = fmaxf(o0.x, 0.f); o0.y = fmaxf(o0.y, 0.f);
                o1.x = fmaxf(o1.x, 0.f); o1.y = fmaxf(o1.y, 0.f);
            }
            if (PAIR) {
                *(uint32_t*)&Ch[(size_t)r0 * N + col] = pack_h2(o0.x, o0.y);
                *(uint32_t*)&Ch[(size_t)(r0 + 8) * N + col] = pack_h2(o1.x, o1.y);
            } else {
                *(float2*)&Cf[(size_t)r0 * N + col] = o0;
                *(float2*)&Cf[(size_t)(r0 + 8) * N + col] = o1;
            }
        }
    }
}

// =================== small SIMT GEMM (head fc2) ===================
__global__ __launch_bounds__(256) void gemm_bias(
    const float* __restrict__ A, const float* __restrict__ W,
    const float* __restrict__ bias, float* __restrict__ C,
    int M, int N, int K)
{
    __shared__ float As[16][68];
    __shared__ float Ws[16][68];
    const int t  = threadIdx.x;
    const int bm = blockIdx.y * 64, bn = blockIdx.x * 64;
    const int tm = (t >> 4) << 2;
    const int tn = (t & 15) << 2;
    const int lr = t >> 2;
    const int lc = (t & 3) << 2;

    float acc[4][4] = {};
    const float* Ap = A + (size_t)(bm + lr) * K + lc;
    const float* Wp = W + (size_t)(bn + lr) * K + lc;

    for (int k0 = 0; k0 < K; k0 += 16) {
        float4 av = *(const float4*)(Ap + k0);
        float4 wv = (bn + lr < N) ? *(const float4*)(Wp + k0) : make_float4(0, 0, 0, 0);
        As[lc+0][lr]=av.x; As[lc+1][lr]=av.y; As[lc+2][lr]=av.z; As[lc+3][lr]=av.w;
        Ws[lc+0][lr]=wv.x; Ws[lc+1][lr]=wv.y; Ws[lc+2][lr]=wv.z; Ws[lc+3][lr]=wv.w;
        __syncthreads();
#pragma unroll
        for (int k = 0; k < 16; k++) {
            float4 a4 = *(const float4*)&As[k][tm];
            float4 w4 = *(const float4*)&Ws[k][tn];
            const float ar[4] = {a4.x, a4.y, a4.z, a4.w};
            const float wr[4] = {w4.x, w4.y, w4.z, w4.w};
#pragma unroll
            for (int r = 0; r < 4; r++)
#pragma unroll
                for (int c = 0; c < 4; c++)
                    acc[r][c] = fmaf(ar[r], wr[c], acc[r][c]);
        }
        __syncthreads();
    }
    if (bn + tn >= N) return;
    float4 bv = *(const float4*)&bias[bn + tn];
    const float bb[4] = {bv.x, bv.y, bv.z, bv.w};
#pragma unroll
    for (int r = 0; r < 4; r++) {
        float4 o; float* op = (float*)&o;
#pragma unroll
        for (int c = 0; c < 4; c++) op[c] = acc[r][c] + bb[c];
        *(float4*)&C[(size_t)(bm + tm + r) * N + bn + tn] = o;
    }
}

// =================== expert select from fused embed [BS,512] ===================
__global__ __launch_bounds__(256) void select_kernel(
    const __half* __restrict__ E2, const int* __restrict__ ST,
    __half* __restrict__ Hh)
{
    const size_t i = (size_t)blockIdx.x * blockDim.x + threadIdx.x;  // uint2 idx of output
    const int row = (int)(i >> 6);                                   // 64 uint2/row (256 halves)
    const int c4  = (int)(i & 63);
    const __half* src = E2 + (size_t)row * 512 + (ST[row] == 0 ? 0 : 256);
    ((uint2*)Hh)[i] = ((const uint2*)src)[c4];
}

// =================== attention: one warp per (batch, head), fp16 in/out =============
__global__ __launch_bounds__(256) void attn_kernel(
    const __half* __restrict__ QKV, __half* __restrict__ Oh)
{
    const int gwarp = (blockIdx.x * blockDim.x + threadIdx.x) >> 5;
    const int lane  = threadIdx.x & 31;
    if (gwarp >= cB * cNH) return;
    const int b = gwarp >> 2, h = gwarp & 3;

    const __half* base = QKV + (size_t)b * cS * 768 + h * 64 + 2 * lane;
    float q[cS][2], kk[cS][2], vv[cS][2];
#pragma unroll
    for (int s = 0; s < cS; s++) {
        const __half* r = base + s * 768;
        float2 qv = unpack_h2(*(const uint32_t*)(r));
        float2 kv = unpack_h2(*(const uint32_t*)(r + 256));
        float2 vw = unpack_h2(*(const uint32_t*)(r + 512));
        q [s][0] = qv.x; q [s][1] = qv.y;
        kk[s][0] = kv.x; kk[s][1] = kv.y;
        vv[s][0] = vw.x; vv[s][1] = vw.y;
    }
    float sc[cS][cS];
#pragma unroll
    for (int i = 0; i < cS; i++)
#pragma unroll
        for (int j = 0; j < cS; j++) {
            float p = q[i][0] * kk[j][0] + q[i][1] * kk[j][1];
#pragma unroll
            for (int o = 16; o > 0; o >>= 1) p += __shfl_xor_sync(0xFFFFFFFFu, p, o);
            sc[i][j] = p * 0.125f;
        }
#pragma unroll
    for (int i = 0; i < cS; i++) {
        float m = sc[i][0];
#pragma unroll
        for (int j = 1; j < cS; j++) m = fmaxf(m, sc[i][j]);
        float e[cS], s = 0.f;
#pragma unroll
        for (int j = 0; j < cS; j++) { e[j] = expf(sc[i][j] - m); s += e[j]; }
        const float inv = 1.f / s;
        float o0 = 0.f, o1 = 0.f;
#pragma unroll
        for (int j = 0; j < cS; j++) {
            const float a = e[j] * inv;
            o0 = fmaf(a, vv[j][0], o0);
            o1 = fmaf(a, vv[j][1], o1);
        }
        const size_t off = (size_t)(b * cS + i) * cE + h * 64 + 2 * lane;
        *(uint32_t*)&Oh[off] = pack_h2(o0, o1);
    }
}

// =================== fused residual + layernorm (fp16 in/out, fp32 math) ============
__global__ __launch_bounds__(256) void add_ln_kernel(
    const __half* __restrict__ Hin, const __half* __restrict__ Cin,
    const float* __restrict__ G, const float* __restrict__ Bv,
    __half* __restrict__ Hout)
{
    const int row  = blockIdx.x * 8 + (threadIdx.x >> 5);
    const int lane = threadIdx.x & 31;
    const size_t rb = (size_t)row * cE;

    float2 v[4];
    float s = 0.f;
#pragma unroll
    for (int i = 0; i < 4; i++) {
        const int e = i * 64 + lane * 2;
        float2 a = unpack_h2(*(const uint32_t*)&Hin[rb + e]);
        float2 b = unpack_h2(*(const uint32_t*)&Cin[rb + e]);
        v[i].x = a.x + b.x; v[i].y = a.y + b.y;
        s += v[i].x + v[i].y;
    }
#pragma unroll
    for (int o = 16; o > 0; o >>= 1) s += __shfl_xor_sync(0xFFFFFFFFu, s, o);
    const float mean = s * (1.f / cE);

    float vs = 0.f;
#pragma unroll
    for (int i = 0; i < 4; i++) {
        const float dx = v[i].x - mean, dy = v[i].y - mean;
        vs += dx * dx + dy * dy;
    }
#pragma unroll
    for (int o = 16; o > 0; o >>= 1) vs += __shfl_xor_sync(0xFFFFFFFFu, vs, o);
    const float rs = rsqrtf(vs * (1.f / cE) + 1e-5f);

#pragma unroll
    for (int i = 0; i < 4; i++) {
        const int e = i * 64 + lane * 2;
        const float2 g = *(const float2*)&G[e];
        const float2 b = *(const float2*)&Bv[e];
        float ox = (v[i].x - mean) * rs * g.x + b.x;
        float oy = (v[i].y - mean) * rs * g.y + b.y;
        *(uint32_t*)&Hout[rb + e] = pack_h2(ox, oy);
    }
}

// =================== final tiny projection ===================
__global__ __launch_bounds__(256) void out_kernel(
    const float* __restrict__ Z, const float* __restrict__ OW,
    const float* __restrict__ OB, float* __restrict__ OUT)
{
    const int b = blockIdx.x * blockDim.x + threadIdx.x;
    if (b >= cB) return;
    float acc[cC];
#pragma unroll
    for (int c = 0; c < cC; c++) acc[c] = OB[c];
    const float* zr = Z + (size_t)b * 64;
    for (int k = 0; k < 64; k++) {
        const float z = zr[k];
#pragma unroll
        for (int c = 0; c < cC; c++) acc[c] = fmaf(z, OW[c * 64 + k], acc[c]);
    }
#pragma unroll
    for (int c = 0; c < cC; c++) OUT[(size_t)b * cC + c] = acc[c];
}

// ---------------- launch ----------------
template<typename T>
static T* symaddr(const void* sym) {
    void* p = nullptr;
    cudaGetSymbolAddress(&p, sym);
    return (T*)p;
}
static void conv_w(const float* src, __half* dst, size_t n) {
    const size_t n4 = n / 4;
    convert_h<<<(unsigned)((n4 + 255) / 256), 256>>>(src, dst, n4);
}

extern "C" void kernel_launch(void* const* d_in, const int* in_sizes, int n_in,
                              void* d_out, int out_size)
{
    const float* x       = (const float*)d_in[0];
    const int*   st      = (const int*)  d_in[1];
    const float* gps_w   = (const float*)d_in[2];
    const float* gps_b   = (const float*)d_in[3];
    const float* ang_w   = (const float*)d_in[4];
    const float* ang_b   = (const float*)d_in[5];
    const float* qkv_w   = (const float*)d_in[6];
    const float* qkv_b   = (const float*)d_in[7];
    const float* attn_ow = (const float*)d_in[8];
    const float* attn_ob = (const float*)d_in[9];
    const float* ln1_g   = (const float*)d_in[10];
    const float* ln1_b   = (const float*)d_in[11];
    const float* ff1_w   = (const float*)d_in[12];
    const float* ff1_b   = (const float*)d_in[13];
    const float* ff2_w   = (const float*)d_in[14];
    const float* ff2_b   = (const float*)d_in[15];
    const float* ln2_g   = (const float*)d_in[16];
    const float* ln2_b   = (const float*)d_in[17];
    const float* fc1_w   = (const float*)d_in[18];
    const float* fc1_b   = (const float*)d_in[19];
    const float* fc2_w   = (const float*)d_in[20];
    const float* fc2_b   = (const float*)d_in[21];
    const float* out_w   = (const float*)d_in[22];
    const float* out_b   = (const float*)d_in[23];
    float* out = (float*)d_out;

    float* Z1  = symaddr<float>(g_Z1);
    float* Z2  = symaddr<float>(g_Z2);
    float* B2  = symaddr<float>(g_bias2);
    __half* X   = symaddr<__half>(g_X);
    __half* Hh  = symaddr<__half>(g_Hh);
    __half* Oh  = symaddr<__half>(g_Oh);
    __half* T   = symaddr<__half>(g_T);
    __half* Th  = symaddr<__half>(g_Th);
    __half* Cbh = symaddr<__half>(g_Cbh);
    __half* W   = symaddr<__half>(g_W);

    static bool attr_set = false;
    if (!attr_set) {
        cudaFuncSetAttribute((const void*)gemm_mma<false,false>,
                             cudaFuncAttributeMaxDynamicSharedMemorySize, GEMM_SMEM);
        cudaFuncSetAttribute((const void*)gemm_mma<true,false>,
                             cudaFuncAttributeMaxDynamicSharedMemorySize, GEMM_SMEM);
        cudaFuncSetAttribute((const void*)gemm_mma<false,true>,
                             cudaFuncAttributeMaxDynamicSharedMemorySize, GEMM_SMEM);
        cudaFuncSetAttribute((const void*)gemm_mma<true,true>,
                             cudaFuncAttributeMaxDynamicSharedMemorySize, GEMM_SMEM);
        attr_set = true;
    }

    // 0. convert input + weights to fp16; concat embed biases
    conv_w(x, X, (size_t)cBS * cD);
    conv_w(gps_w,   W + OFF_GPS, 131072);
    conv_w(ang_w,   W + OFF_ANG, 131072);
    conv_w(qkv_w,   W + OFF_QKV, 393216);
    conv_w(attn_ow, W + OFF_OW,  131072);
    conv_w(ff1_w,   W + OFF_FF1, 1048576);
    conv_w(ff2_w,   W + OFF_FF2, 1048576);
    conv_w(fc1_w,   W + OFF_FC1, 163840);
    concat2_kernel<<<2, 256>>>(gps_b, ang_b, B2, 256);

    const int MT = cBS / 128;   // 1280 row tiles

    // 1. fused dual-expert embed (N=512: [gps|ang]) + select
    gemm_mma<true,true><<<dim3(512/128, MT), 256, GEMM_SMEM>>>(
        X, W + OFF_GPS, B2, nullptr, T, cBS, 512, cD);
    select_kernel<<<(cBS * cE / 4) / 256, 256>>>(T, st, Hh);

    // 2. transformer layers
    for (int l = 0; l < cL; l++) {
        const __half* qw  = W + OFF_QKV + (size_t)l * 768 * cE;
        const __half* ow  = W + OFF_OW  + (size_t)l * cE * cE;
        const __half* f1w = W + OFF_FF1 + (size_t)l * cF * cE;
        const __half* f2w = W + OFF_FF2 + (size_t)l * cE * cF;
        const float* qb  = qkv_b   + (size_t)l * 3 * cE;
        const float* ob  = attn_ob + (size_t)l * cE;
        const float* f1b = ff1_b   + (size_t)l * cF;
        const float* f2b = ff2_b   + (size_t)l * cE;

        gemm_mma<false,true><<<dim3(768/128, MT), 256, GEMM_SMEM>>>(
            Hh, qw, qb, nullptr, T, cBS, 768, cE);
        attn_kernel<<<(cB * cNH * 32) / 256, 256>>>(T, Oh);
        gemm_mma<false,true><<<dim3(cE/128, MT), 256, GEMM_SMEM>>>(
            Oh, ow, ob, nullptr, Cbh, cBS, cE, cE);
        add_ln_kernel<<<cBS / 8, 256>>>(Hh, Cbh, ln1_g + l * cE, ln1_b + l * cE, Hh);
        gemm_mma<true,true><<<dim3(cF/128, MT), 256, GEMM_SMEM>>>(
            Hh, f1w, f1b, nullptr, Th, cBS, cF, cE);
        gemm_mma<false,true><<<dim3(cE/128, MT), 256, GEMM_SMEM>>>(
            Th, f2w, f2b, nullptr, Cbh, cBS, cE, cF);
        add_ln_kernel<<<cBS / 8, 256>>>(Hh, Cbh, ln2_g + l * cE, ln2_b + l * cE, Hh);
    }

    // 3. head: Hh viewed as [B,1280]
    gemm_mma<false,false><<<dim3(1, cB/128), 256, GEMM_SMEM>>>(
        Hh, W + OFF_FC1, fc1_b, Z1, nullptr, cB, 128, cZK);
    gemm_bias<<<dim3(1, cB/64), 256>>>(Z1, fc2_w, fc2_b, Z2, cB, 64, 128);
    out_kernel<<<cB / 256, 256>>>(Z2, out_w, out_b, out);
}